// round 11
// baseline (speedup 1.0000x reference)
#include <cuda_runtime.h>
#include <cstdint>

#define IMG_W 200
#define CHAN 512
#define NF4  (CHAN / 4)
#define POOL 7
#define NROI 300
#define NPOS (NROI * POOL * POOL)   // 14700

#define CP_ASYNC16(smem_u32_, gptr_) \
    asm volatile("cp.async.ca.shared.global [%0], [%1], 16;" \
                 :: "r"(smem_u32_), "l"(gptr_) : "memory")
#define CP_COMMIT() asm volatile("cp.async.commit_group;" ::: "memory")
#define CP_WAIT(n_)  asm volatile("cp.async.wait_group %0;" :: "n"(n_) : "memory")

struct Pos {
    int o00, o01, o10, o11;   // float4-unit offsets (thread-specific)
    float fx, fy;
    int opos;                 // output float4 index
};

__device__ __forceinline__ Pos setup_pos(const int* __restrict__ rois, int pos_id, int tid)
{
    const int roi = pos_id / (POOL * POOL);
    const int pp  = pos_id % (POOL * POOL);
    const int gy  = pp / POOL;
    const int gx  = pp % POOL;

    const int4 r = __ldg((const int4*)rois + roi);
    const int x0 = r.x, y0 = r.y, w = r.z, h = r.w;

    const float ys = (float)y0 + (float)gy * ((float)h / (float)POOL);
    const float xs = (float)x0 + (float)gx * ((float)w / (float)POOL);
    const int ty = (int)floorf(ys);
    const int tx = (int)floorf(xs);

    Pos p;
    p.fy = ys - (float)ty;
    p.fx = xs - (float)tx;
    const int by = min(ty + 1, y0 + h - 1);
    const int bx = min(tx + 1, x0 + w - 1);
    const bool lx = (p.fx != 0.0f);
    const bool ly = (p.fy != 0.0f);

    p.o00 = (ty * IMG_W + tx) * NF4 + tid;
    p.o01 = lx ? (ty * IMG_W + bx) * NF4 + tid : p.o00;
    p.o10 = ly ? (by * IMG_W + tx) * NF4 + tid : p.o00;
    p.o11 = lx ? (ly ? (by * IMG_W + bx) * NF4 + tid : p.o01) : p.o10;
    p.opos = pos_id * NF4 + tid;
    return p;
}

// Two positions per block, cp.async double-buffer. Each thread fetches its own
// 16B of each corner row into smem and later consumes exactly those bytes, so
// no block barrier is needed — only cp.async.wait_group.
__global__ void __launch_bounds__(128) roi_pool_cpasync_kernel(
    const float* __restrict__ img,   // [200,200,512]
    const int*   __restrict__ rois,  // [300,4]
    float*       __restrict__ out)   // [300,7,7,512]
{
    __shared__ alignas(16) float4 buf[2][4][128];   // 16 KB

    const int tid  = threadIdx.x;
    const int pos0 = blockIdx.x * 2;
    const int pos1 = pos0 + 1;

    const Pos a = setup_pos(rois, pos0, tid);
    const Pos b = setup_pos(rois, pos1, tid);

    const float4* __restrict__ base = (const float4*)img;

    // Prefetch position 0 into slot 0.
    {
        const uint32_t s = (uint32_t)__cvta_generic_to_shared(&buf[0][0][tid]);
        CP_ASYNC16(s + 0 * 2048, base + a.o00);
        CP_ASYNC16(s + 1 * 2048, base + a.o01);
        CP_ASYNC16(s + 2 * 2048, base + a.o10);
        CP_ASYNC16(s + 3 * 2048, base + a.o11);
        CP_COMMIT();
    }
    // Prefetch position 1 into slot 1.
    {
        const uint32_t s = (uint32_t)__cvta_generic_to_shared(&buf[1][0][tid]);
        CP_ASYNC16(s + 0 * 2048, base + b.o00);
        CP_ASYNC16(s + 1 * 2048, base + b.o01);
        CP_ASYNC16(s + 2 * 2048, base + b.o10);
        CP_ASYNC16(s + 3 * 2048, base + b.o11);
        CP_COMMIT();
    }

    float4* __restrict__ out4 = (float4*)out;

    // Consume position 0 (slot 0) while position 1 is still in flight.
    CP_WAIT(1);
    {
        const float4 v00 = buf[0][0][tid];
        const float4 v01 = buf[0][1][tid];
        const float4 v10 = buf[0][2][tid];
        const float4 v11 = buf[0][3][tid];
        const float fx = a.fx, fy = a.fy;
        const float omfx = 1.0f - fx, omfy = 1.0f - fy;
        float4 res;
        res.x = omfy * (omfx * v00.x + fx * v01.x) + fy * (omfx * v10.x + fx * v11.x);
        res.y = omfy * (omfx * v00.y + fx * v01.y) + fy * (omfx * v10.y + fx * v11.y);
        res.z = omfy * (omfx * v00.z + fx * v01.z) + fy * (omfx * v10.z + fx * v11.z);
        res.w = omfy * (omfx * v00.w + fx * v01.w) + fy * (omfx * v10.w + fx * v11.w);
        out4[a.opos] = res;
    }

    // Consume position 1 (slot 1).
    CP_WAIT(0);
    {
        const float4 v00 = buf[1][0][tid];
        const float4 v01 = buf[1][1][tid];
        const float4 v10 = buf[1][2][tid];
        const float4 v11 = buf[1][3][tid];
        const float fx = b.fx, fy = b.fy;
        const float omfx = 1.0f - fx, omfy = 1.0f - fy;
        float4 res;
        res.x = omfy * (omfx * v00.x + fx * v01.x) + fy * (omfx * v10.x + fx * v11.x);
        res.y = omfy * (omfx * v00.y + fx * v01.y) + fy * (omfx * v10.y + fx * v11.y);
        res.z = omfy * (omfx * v00.z + fx * v01.z) + fy * (omfx * v10.z + fx * v11.z);
        res.w = omfy * (omfx * v00.w + fx * v01.w) + fy * (omfx * v10.w + fx * v11.w);
        out4[b.opos] = res;
    }
}

extern "C" void kernel_launch(void* const* d_in, const int* in_sizes, int n_in,
                              void* d_out, int out_size) {
    const float* img  = (const float*)d_in[0];
    const int*   rois = (const int*)d_in[1];
    float*       out  = (float*)d_out;

    roi_pool_cpasync_kernel<<<NPOS / 2, 128>>>(img, rois, out);
}

// round 12
// speedup vs baseline: 1.3645x; 1.3645x over previous
#include <cuda_runtime.h>

#define IMG_W 200
#define CHAN 512
#define NF4  (CHAN / 4)
#define POOL 7
#define NROI 300
#define NPOS (NROI * POOL * POOL)   // 14700

struct Pos {
    int o00, o01, o10, o11;   // float4-unit offsets (block-uniform base + lane)
    float fx, fy;
    bool lx, ly;
};

__device__ __forceinline__ Pos setup_pos(int4 r, int gy, int gx, int c4)
{
    const int x0 = r.x, y0 = r.y, w = r.z, h = r.w;

    // Reference numerics: ys = y0 + gy*(h/7.0f)
    const float ys = (float)y0 + (float)gy * ((float)h / (float)POOL);
    const float xs = (float)x0 + (float)gx * ((float)w / (float)POOL);
    const int ty = (int)floorf(ys);
    const int tx = (int)floorf(xs);

    Pos p;
    p.fy = ys - (float)ty;
    p.fx = xs - (float)tx;
    p.ly = (p.fy != 0.0f);
    p.lx = (p.fx != 0.0f);

    const int by = min(ty + 1, y0 + h - 1);
    const int bx = min(tx + 1, x0 + w - 1);

    p.o00 = (ty * IMG_W + tx) * NF4 + c4;
    p.o01 = (ty * IMG_W + bx) * NF4 + c4;
    p.o10 = (by * IMG_W + tx) * NF4 + c4;
    p.o11 = (by * IMG_W + bx) * NF4 + c4;
    return p;
}

__device__ __forceinline__ float4 lerp2d(float4 v00, float4 v01, float4 v10, float4 v11,
                                         float fx, float fy)
{
    const float omfx = 1.0f - fx;
    const float omfy = 1.0f - fy;
    float4 res;
    res.x = omfy * (omfx * v00.x + fx * v01.x) + fy * (omfx * v10.x + fx * v11.x);
    res.y = omfy * (omfx * v00.y + fx * v01.y) + fy * (omfx * v10.y + fx * v11.y);
    res.z = omfy * (omfx * v00.z + fx * v01.z) + fy * (omfx * v10.z + fx * v11.z);
    res.w = omfy * (omfx * v00.w + fx * v01.w) + fy * (omfx * v10.w + fx * v11.w);
    return res;
}

// Two pool positions per block (consecutive, same roi row pair handling via
// shared roi decode). 128 threads = one float4 lane per position. All needed
// loads are issued back-to-back (block-uniform predicates); zero-weight
// corner loads are skipped entirely.
__global__ void __launch_bounds__(128) roi_pool_kernel(
    const float* __restrict__ img,   // [200,200,512]
    const int*   __restrict__ rois,  // [300,4] = (x,y,w,h)
    float*       __restrict__ out)   // [300,7,7,512]
{
    const int pos0 = blockIdx.x * 2;
    const int c4 = threadIdx.x;

    // Decode once; position 1 = position 0 + 1 within the same 49-grid except
    // at the wrap (gx==6 -> gy+1, or roi+1). Handle wrap cheaply.
    const int roi0 = pos0 / (POOL * POOL);
    const int pp0  = pos0 % (POOL * POOL);
    const int gy0  = pp0 / POOL;
    const int gx0  = pp0 % POOL;

    // pos0 is even; pos1 = pos0+1 (never crosses roi since 49 odd? 49 is odd,
    // so pairs CAN cross roi boundary -> recompute robustly for pos1).
    const int pos1 = pos0 + 1;
    const int roi1 = pos1 / (POOL * POOL);
    const int pp1  = pos1 % (POOL * POOL);
    const int gy1  = pp1 / POOL;
    const int gx1  = pp1 % POOL;

    const int4 r0 = __ldg((const int4*)rois + roi0);
    const int4 r1 = (roi1 == roi0) ? r0 : __ldg((const int4*)rois + roi1);

    const Pos a = setup_pos(r0, gy0, gx0, c4);
    const Pos b = setup_pos(r1, gy1, gx1, c4);

    const float4* __restrict__ base = (const float4*)img;
    const float4 zero = make_float4(0.f, 0.f, 0.f, 0.f);

    // Front-issue all needed loads (block-uniform conditions).
    const float4 a00 = __ldg(base + a.o00);
    const float4 b00 = __ldg(base + b.o00);

    float4 a01 = zero, a10 = zero, a11 = zero;
    float4 b01 = zero, b10 = zero, b11 = zero;
    if (a.lx)         a01 = __ldg(base + a.o01);
    if (b.lx)         b01 = __ldg(base + b.o01);
    if (a.ly)         a10 = __ldg(base + a.o10);
    if (b.ly)         b10 = __ldg(base + b.o10);
    if (a.lx && a.ly) a11 = __ldg(base + a.o11);
    if (b.lx && b.ly) b11 = __ldg(base + b.o11);

    float4* __restrict__ out4 = (float4*)out;
    out4[pos0 * NF4 + c4] = lerp2d(a00, a01, a10, a11, a.fx, a.fy);
    out4[pos1 * NF4 + c4] = lerp2d(b00, b01, b10, b11, b.fx, b.fy);
}

extern "C" void kernel_launch(void* const* d_in, const int* in_sizes, int n_in,
                              void* d_out, int out_size) {
    const float* img  = (const float*)d_in[0];
    const int*   rois = (const int*)d_in[1];
    float*       out  = (float*)d_out;

    roi_pool_kernel<<<NPOS / 2, 128>>>(img, rois, out);
}